// round 1
// baseline (speedup 1.0000x reference)
#include <cuda_runtime.h>

// FoldNd (col2im): B=16, C=64, K=3, H=W=128, PAD=1, STR=1, DIL=1
// input  : (B, C*K*K, LH*LW) = (16, 576, 16384) float32
// output : (B, C, H, W)      = (16, 64, 128, 128) float32
//
// Gather formulation: out[b,c,h,w] = sum_{kh,kw} in[b, c*9+kh*3+kw, lh*128+lw]
// where lh = h + PAD - kh, lw = w + PAD - kw, contributions only when
// 0 <= lh < LH and 0 <= lw < LW. Each input element is read at most once.

namespace {
constexpr int B = 16;
constexpr int C = 64;
constexpr int H = 128;
constexpr int W = 128;
constexpr int K = 3;
constexpr int PAD = 1;
constexpr int PLANE = H * W;        // 16384 (= LH*LW since LH=H, LW=W here)
constexpr int NOUT = B * C * H * W; // 16,777,216
}

__global__ void __launch_bounds__(256) fold_gather_kernel(
    const float* __restrict__ in, float* __restrict__ out)
{
    int idx = blockIdx.x * blockDim.x + threadIdx.x;
    if (idx >= NOUT) return;

    int w  = idx & (W - 1);
    int h  = (idx >> 7) & (H - 1);
    int bc = idx >> 14;            // b*64 + c
    // plane base: (b*C*9 + c*9) * PLANE = bc*9*PLANE  (since channels are
    // laid out as b-major then c-major with 9 k-planes per (b,c))
    const float* base = in + (long long)bc * 9 * PLANE;

    float acc = 0.0f;
    #pragma unroll
    for (int kh = 0; kh < K; ++kh) {
        int lh = h + PAD - kh;
        if ((unsigned)lh < (unsigned)H) {
            const float* row = base + kh * 3 * PLANE + lh * W;
            #pragma unroll
            for (int kw = 0; kw < K; ++kw) {
                int lw = w + PAD - kw;
                if ((unsigned)lw < (unsigned)W) {
                    acc += __ldg(row + kw * PLANE + lw);
                }
            }
        }
    }
    out[idx] = acc;
}

extern "C" void kernel_launch(void* const* d_in, const int* in_sizes, int n_in,
                              void* d_out, int out_size)
{
    const float* in = (const float*)d_in[0];
    float* out = (float*)d_out;
    const int threads = 256;
    const int blocks = (NOUT + threads - 1) / threads;
    fold_gather_kernel<<<blocks, threads>>>(in, out);
}

// round 2
// speedup vs baseline: 1.1888x; 1.1888x over previous
#include <cuda_runtime.h>

// FoldNd (col2im): B=16, C=64, K=3, H=W=128, PAD=1, STR=1, DIL=1
// Gather form, vectorized: each thread computes 4 consecutive output pixels
// (one float4) from 9 input planes using 3x LDG.128 + 2 predicated scalar
// loads per kernel row, then one STG.128.
//
// out[b,c,h,w] = sum_{kh,kw} in[(b*64+c)*9 + kh*3+kw][ (h+1-kh)*128 + (w+1-kw) ]
// with bounds predication on (h+1-kh) in [0,128) and (w+1-kw) in [0,128).

namespace {
constexpr int H = 128;
constexpr int W = 128;
constexpr int PLANE = H * W;            // 16384
constexpr int NOUT = 16 * 64 * H * W;   // 16,777,216
constexpr int NVEC = NOUT / 4;          // 4,194,304
}

__global__ void __launch_bounds__(256) fold_vec4_kernel(
    const float* __restrict__ in, float* __restrict__ out)
{
    int v = blockIdx.x * blockDim.x + threadIdx.x;
    if (v >= NVEC) return;

    int w0 = (v & 31) << 2;          // 0,4,...,124
    int h  = (v >> 5) & (H - 1);
    int bc = v >> 12;                // b*64 + c

    const float* base = in + (long long)bc * 9 * PLANE;

    float4 acc = make_float4(0.f, 0.f, 0.f, 0.f);

    #pragma unroll
    for (int kh = 0; kh < 3; ++kh) {
        int lh = h + 1 - kh;
        if ((unsigned)lh < (unsigned)H) {
            const float* r0 = base + (kh * 3 + 0) * PLANE + lh * W; // kw=0 plane
            const float* r1 = r0 + PLANE;                            // kw=1
            const float* r2 = r1 + PLANE;                            // kw=2

            // aligned 16B vector loads
            float4 A  = *reinterpret_cast<const float4*>(r0 + w0);
            float4 Bv = *reinterpret_cast<const float4*>(r1 + w0);
            float4 Cv = *reinterpret_cast<const float4*>(r2 + w0);

            // boundary scalars (predicated)
            // kw=0 needs lw = w+1 -> element w0+4 for the 4th output
            float a4  = (w0 < W - 4) ? __ldg(r0 + w0 + 4) : 0.f;
            // kw=2 needs lw = w-1 -> element w0-1 for the 1st output
            float cm1 = (w0 > 0)     ? __ldg(r2 + w0 - 1) : 0.f;

            // output w0+j gets: kw0 -> A[j+1] (a4 for j=3),
            //                   kw1 -> Bv[j],
            //                   kw2 -> Cv[j-1] (cm1 for j=0)
            acc.x += A.y + Bv.x + cm1;
            acc.y += A.z + Bv.y + Cv.x;
            acc.z += A.w + Bv.z + Cv.y;
            acc.w += a4  + Bv.w + Cv.z;
        }
    }

    reinterpret_cast<float4*>(out)[v] = acc;
}

extern "C" void kernel_launch(void* const* d_in, const int* in_sizes, int n_in,
                              void* d_out, int out_size)
{
    const float* in = (const float*)d_in[0];
    float* out = (float*)d_out;
    const int threads = 256;
    const int blocks = (NVEC + threads - 1) / threads;
    fold_vec4_kernel<<<blocks, threads>>>(in, out);
}